// round 3
// baseline (speedup 1.0000x reference)
#include <cuda_runtime.h>
#include <math.h>

#define T_LEN 2000
#define FC    514           // 257 * 2
#define NSER  8224          // 16 * 514
#define CH    40            // number of time chunks
#define LCH   50            // chunk length
#define GRP   16            // series per block
#define NPAIR 8             // float2 pairs per block
#define BTHREADS (NPAIR * CH)   // 320

// Per-t constants: (w, a=1-w, b=w*a, bP = b * Ppre) where Ppre is the
// within-chunk prefix product of a (data-independent).
__device__ float4 g_c4[T_LEN];
// Per-chunk constants: (P = prod a over chunk, gamma = sum suffix-decayed b*Ppre^2)
__device__ float2 g_ck[CH];

__global__ void coef_kernel() {
    int c = threadIdx.x;          // one thread per chunk, 40 threads
    if (c >= CH) return;
    double b  = (double)0.99f;
    double c1 = (double)(1.0f - 0.99f);   // exact
    double Ppre = 1.0, ga = 0.0;
    for (int u = 0; u < LCH; u++) {
        int t = c * LCH + u;
        double bt = pow(b, (double)(t + 1));
        double w  = c1 / (1.0 - bt);      // w_0 == 1 exactly
        double a  = 1.0 - w;
        double bb = w * a;
        g_c4[t] = make_float4((float)w, (float)a, (float)bb, (float)(bb * Ppre));
        ga = a * ga + bb * Ppre * Ppre;   // suffix decay via forward recurrence
        Ppre *= a;
    }
    g_ck[c] = make_float2((float)Ppre, (float)ga);
}

// Fused: pass1 (chunk transfer coeffs) -> combine (serial over 40 chunks,
// in smem) -> pass2 (replay + emit). One block owns 16 series (8 float2 pairs).
__global__ __launch_bounds__(BTHREADS)
void ewma_fused_kernel(const float* __restrict__ in, float* __restrict__ out) {
    __shared__ float sQ [CH][GRP];
    __shared__ float sAl[CH][GRP];
    __shared__ float sBe[CH][GRP];
    __shared__ float sV2[CH][GRP];
    __shared__ float sS [CH][GRP];

    int tid = threadIdx.x;
    int pr  = tid & (NPAIR - 1);      // pair 0..7
    int c   = tid >> 3;               // chunk 0..39

    int gpair = blockIdx.x * NPAIR + pr;      // global pair id (0..4111)
    int n  = gpair / (FC / 2);                // 257 pairs per n
    int fc = (gpair - n * (FC / 2)) * 2;
    size_t base = ((size_t)n * T_LEN + (size_t)c * LCH) * FC + fc;
    const float2* xp = (const float2*)(in  + base);
    float2*       yp = (float2*)(out + base);
    const float4* cf = g_c4 + c * LCH;

    // ---- pass 1: chunk-local (Q, alpha, beta-hat), zero start state ----
    float Q0 = 0.f, Q1 = 0.f, al0 = 0.f, al1 = 0.f, be0 = 0.f, be1 = 0.f;
#pragma unroll 10
    for (int u = 0; u < LCH; u++) {
        float4 k = __ldg(cf + u);                      // (w, a, b, bP)
        float2 x = __ldg(xp + (size_t)u * (FC / 2));
        float u0 = x.x - Q0;
        float u1 = x.y - Q1;
        Q0 = fmaf(k.x, u0, Q0);
        Q1 = fmaf(k.x, u1, Q1);
        float b0 = k.z * u0, b1 = k.z * u1;
        al0 = fmaf(k.y, al0, b0 * u0);
        al1 = fmaf(k.y, al1, b1 * u1);
        be0 = fmaf(k.y, be0, k.w * u0);
        be1 = fmaf(k.y, be1, k.w * u1);
    }
    int s0 = pr * 2;
    sQ [c][s0] = Q0;  sQ [c][s0 + 1] = Q1;
    sAl[c][s0] = al0; sAl[c][s0 + 1] = al1;
    sBe[c][s0] = be0; sBe[c][s0 + 1] = be1;
    __syncthreads();

    // ---- combine: serial over chunks, 16 threads (one per series) ----
    if (tid < GRP) {
        float v2 = 0.f, S = 0.f;
#pragma unroll 8
        for (int k = 0; k < CH; k++) {
            float2 pg = __ldg(&g_ck[k]);               // (P, gamma)
            sV2[k][tid] = v2;
            sS [k][tid] = S;
            float q  = sQ [k][tid];
            float al = sAl[k][tid];
            float be = sBe[k][tid];
            // S' = P*S + al + v2*(gamma*v2 - 2*be);  v2' = P*v2 + Q
            float corr = fmaf(pg.y, v2, -2.0f * be);
            float add  = fmaf(v2, corr, al);
            S  = fmaf(pg.x, S, add);
            v2 = fmaf(pg.x, v2, q);
        }
    }
    __syncthreads();

    // ---- pass 2: replay with exact start state, emit outputs ----
    float v20 = sV2[c][s0], v21 = sV2[c][s0 + 1];
    float S0  = sS [c][s0], S1  = sS [c][s0 + 1];
#pragma unroll 10
    for (int u = 0; u < LCH; u++) {
        float4 k = __ldg(cf + u);
        float2 x = __ldg(xp + (size_t)u * (FC / 2));
        float d0 = x.x - v20;
        float d1 = x.y - v21;
        v20 = fmaf(k.x, d0, v20);
        v21 = fmaf(k.x, d1, v21);
        float bd0 = k.z * d0, bd1 = k.z * d1;
        S0 = fmaf(k.y, S0, bd0 * d0);
        S1 = fmaf(k.y, S1, bd1 * d1);
        float r0 = rsqrtf(fmaxf(S0, 0.0f) + 1e-5f);
        float r1 = rsqrtf(fmaxf(S1, 0.0f) + 1e-5f);
        float2 y;
        y.x = (k.y * d0) * r0;
        y.y = (k.y * d1) * r1;
        __stcs(yp + (size_t)u * (FC / 2), y);
    }
}

extern "C" void kernel_launch(void* const* d_in, const int* in_sizes, int n_in,
                              void* d_out, int out_size) {
    const float* s = (const float*)d_in[0];
    float* out = (float*)d_out;
    coef_kernel<<<1, 64>>>();
    ewma_fused_kernel<<<NSER / GRP, BTHREADS>>>(s, out);   // 514 blocks
}

// round 4
// speedup vs baseline: 2.5916x; 2.5916x over previous
#include <cuda_runtime.h>
#include <math.h>

#define T_LEN  2000
#define FC     514            // 257 * 2
#define NSER   8224           // 16 * 514
#define NPAIRS (NSER / 2)     // 4112 float2 series-pairs
#define FC2    (FC / 2)       // 257 pairs per row
#define CH     40             // number of time chunks
#define LCH    50             // chunk length

// Per-t constants: (w, a = 1-w, b = w*a, bP = b * Ppre_u) — all data-independent.
__device__ float4 g_c4[T_LEN];
// Per-chunk constants: (P, gamma), closed-form.
__device__ float2 g_ck[CH];
// Per (chunk, series) scratch from pass1 / combine.
__device__ float g_q [CH * NSER];
__device__ float g_al[CH * NSER];
__device__ float g_be[CH * NSER];
__device__ float g_v2[CH * NSER];
__device__ float g_s [CH * NSER];

__global__ void coef_kernel() {
    int t = blockIdx.x * blockDim.x + threadIdx.x;
    if (t >= T_LEN) return;
    const double b  = (double)0.99f;
    const double c1 = (double)(1.0f - 0.99f);   // exact
    int c  = t / LCH;
    int t0 = c * LCH;
    int u  = t - t0;

    double bt1 = pow(b, (double)(t + 1));       // beta^{t+1}
    double w   = c1 / (1.0 - bt1);              // w_0 == 1 exactly
    double a   = 1.0 - w;
    double bb  = w * a;

    // Ppre_u = beta^u * (1 - beta^t0) / (1 - beta^t)   (u >= 1); Ppre_0 = 1.
    double Ppre;
    if (u == 0) Ppre = 1.0;
    else        Ppre = pow(b, (double)u) * (1.0 - pow(b, (double)t0))
                       / (1.0 - pow(b, (double)t));
    g_c4[t] = make_float4((float)w, (float)a, (float)bb, (float)(bb * Ppre));

    if (u == 0) {
        // P_c = beta^L (1-beta^t0)/(1-beta^{t0+L});  gamma = beta^{-t0} P (1 - beta^{-L} P)
        double P  = pow(b, (double)LCH) * (1.0 - pow(b, (double)t0))
                    / (1.0 - pow(b, (double)(t0 + LCH)));
        double ga = pow(b, -(double)t0) * P * (1.0 - pow(b, -(double)LCH) * P);
        g_ck[c] = make_float2((float)P, (float)ga);
    }
}

// Pass 1: per (chunk, pair) compute (Q, alpha, beta-hat) from zero start.
__global__ __launch_bounds__(256)
void pass1_kernel(const float* __restrict__ in) {
    int pr = blockIdx.x * 256 + threadIdx.x;
    int c  = blockIdx.y;
    if (pr >= NPAIRS) return;
    int n  = pr / FC2;
    int fp = pr - n * FC2;
    const float2* xp = (const float2*)in
                     + ((size_t)n * T_LEN + (size_t)c * LCH) * FC2 + fp;
    const float4* cf = g_c4 + c * LCH;

    float Q0 = 0.f, Q1 = 0.f, al0 = 0.f, al1 = 0.f, be0 = 0.f, be1 = 0.f;
#pragma unroll 10
    for (int u = 0; u < LCH; u++) {
        float4 k = __ldg(cf + u);                // (w, a, b, bP)
        float2 x = __ldg(xp + (size_t)u * FC2);
        float u0 = x.x - Q0;
        float u1 = x.y - Q1;
        Q0 = fmaf(k.x, u0, Q0);
        Q1 = fmaf(k.x, u1, Q1);
        al0 = fmaf(k.y, al0, (k.z * u0) * u0);
        al1 = fmaf(k.y, al1, (k.z * u1) * u1);
        be0 = fmaf(k.y, be0, k.w * u0);
        be1 = fmaf(k.y, be1, k.w * u1);
    }
    int idx = c * NSER + pr * 2;
    *(float2*)&g_q [idx] = make_float2(Q0, Q1);
    *(float2*)&g_al[idx] = make_float2(al0, al1);
    *(float2*)&g_be[idx] = make_float2(be0, be1);
}

// Combine: serial over the 40 chunks per series-pair.
__global__ __launch_bounds__(256)
void combine_kernel() {
    int pr = blockIdx.x * 256 + threadIdx.x;
    if (pr >= NPAIRS) return;
    float v20 = 0.f, v21 = 0.f, S0 = 0.f, S1 = 0.f;
#pragma unroll 8
    for (int c = 0; c < CH; c++) {
        int idx = c * NSER + pr * 2;
        float2 pg = __ldg(&g_ck[c]);             // (P, gamma)
        float2 q  = __ldg((const float2*)&g_q [idx]);
        float2 al = __ldg((const float2*)&g_al[idx]);
        float2 be = __ldg((const float2*)&g_be[idx]);
        *(float2*)&g_v2[idx] = make_float2(v20, v21);
        *(float2*)&g_s [idx] = make_float2(S0, S1);
        // S' = P*S + al + v2*(gamma*v2 - 2*be);  v2' = P*v2 + Q
        float c0 = fmaf(pg.y, v20, -2.0f * be.x);
        float c1 = fmaf(pg.y, v21, -2.0f * be.y);
        S0 = fmaf(pg.x, S0, fmaf(v20, c0, al.x));
        S1 = fmaf(pg.x, S1, fmaf(v21, c1, al.y));
        v20 = fmaf(pg.x, v20, q.x);
        v21 = fmaf(pg.x, v21, q.y);
    }
}

// Pass 2: replay each chunk with exact start state, emit outputs.
__global__ __launch_bounds__(256)
void pass2_kernel(const float* __restrict__ in, float* __restrict__ out) {
    int pr = blockIdx.x * 256 + threadIdx.x;
    int c  = blockIdx.y;
    if (pr >= NPAIRS) return;
    int n  = pr / FC2;
    int fp = pr - n * FC2;
    size_t base = ((size_t)n * T_LEN + (size_t)c * LCH) * FC2 + fp;
    const float2* xp = (const float2*)in  + base;
    float2*       yp = (float2*)out + base;
    const float4* cf = g_c4 + c * LCH;

    int idx = c * NSER + pr * 2;
    float2 v2 = __ldg((const float2*)&g_v2[idx]);
    float2 S  = __ldg((const float2*)&g_s [idx]);
    float v20 = v2.x, v21 = v2.y, S0 = S.x, S1 = S.y;

#pragma unroll 10
    for (int u = 0; u < LCH; u++) {
        float4 k = __ldg(cf + u);                // (w, a, b, -)
        float2 x = __ldg(xp + (size_t)u * FC2);
        float d0 = x.x - v20;
        float d1 = x.y - v21;
        v20 = fmaf(k.x, d0, v20);
        v21 = fmaf(k.x, d1, v21);
        S0 = fmaf(k.y, S0, (k.z * d0) * d0);
        S1 = fmaf(k.y, S1, (k.z * d1) * d1);
        float r0 = rsqrtf(fmaxf(S0, 0.0f) + 1e-5f);
        float r1 = rsqrtf(fmaxf(S1, 0.0f) + 1e-5f);
        float2 y;
        y.x = (k.y * d0) * r0;
        y.y = (k.y * d1) * r1;
        __stcs(yp + (size_t)u * FC2, y);
    }
}

extern "C" void kernel_launch(void* const* d_in, const int* in_sizes, int n_in,
                              void* d_out, int out_size) {
    const float* s = (const float*)d_in[0];
    float* out = (float*)d_out;
    coef_kernel<<<(T_LEN + 127) / 128, 128>>>();
    dim3 grid((NPAIRS + 255) / 256, CH);         // (17, 40)
    pass1_kernel<<<grid, 256>>>(s);
    combine_kernel<<<(NPAIRS + 255) / 256, 256>>>();
    pass2_kernel<<<grid, 256>>>(s, out);
}